// round 10
// baseline (speedup 1.0000x reference)
#include <cuda_runtime.h>

// Appro_WAConv2d: depthwise 7x7 conv with mantissa-approximation factor.
//   term = x*w*(f1+f2-1)/(f1*f2) = u*w + s*(w/f2),  u = x/f1, s = x - u
// Packed f32x2: smem {u,s} float2, weights {w, w/f2}; one fma.rn.f32x2/tap.
// Round-10: keep R9's persistent double-buffered pipeline; cut L1 crossbar
// phases by loading weights as LDS.128 pair-broadcasts (one 16B broadcast
// feeds two j-taps / 4 FFMA2). Weight loads 98 -> 56 per thread, total
// phases/warp/tile ~238 -> ~196, instructions/thread -11%.

#define B_   4
#define C_   192
#define H_   56
#define W_   56
#define K_   7
#define PAD_ 3
#define HR    28            // output rows per tile (half plane)
#define SMROWS 34           // 28 + 2*3 halo rows
#define SMCOLS 62           // 56 + 2*3 halo cols (used)
#define SR    64            // smem row stride in float2 (pow2 indexing)
#define NTHR  392
#define CELLS (SMROWS * SR) // 2176
#define NTILES (B_ * C_ * 2)  // 1536
#define NBLK  456           // 152 SMs * 3 resident blocks

// mantissa map: a=|v|+1e-7; mant in [1,2); result in [0.75,1.5). Bit trick:
__device__ __forceinline__ float mant_map(float v) {
    float a = fabsf(v) + 1e-7f;
    unsigned b = __float_as_uint(a);
    unsigned m = b & 0x007FFFFFu;
    unsigned e = (m & 0x00400000u) ? 0x3F000000u : 0x3F800000u; // exp 126/127
    return __uint_as_float(m | e);
}

__device__ __forceinline__ unsigned long long fma2(unsigned long long a,
                                                   unsigned long long b,
                                                   unsigned long long c) {
    unsigned long long d;
    asm("fma.rn.f32x2 %0, %1, %2, %3;" : "=l"(d) : "l"(a), "l"(b), "l"(c));
    return d;
}

__device__ __forceinline__ float pairsum(unsigned long long v) {
    return __uint_as_float((unsigned)v) + __uint_as_float((unsigned)(v >> 32));
}

__global__ __launch_bounds__(NTHR, 3)
void waconv_kernel(const float* __restrict__ x,
                   const float* __restrict__ w,
                   float* __restrict__ out) {
    __shared__ __align__(16) float2 sm[2][CELLS];     // {u, s} interleaved
    __shared__ __align__(16) float2 sw[2][K_ * 8];    // {w, w/f2}, rows of 8

    const int tid = threadIdx.x;
    const int t0 = (int)(((long long)blockIdx.x       * NTILES) / NBLK);
    const int t1 = (int)(((long long)(blockIdx.x + 1) * NTILES) / NBLK);

    const int ty = tid / 28;               // 0..13
    const int tx = tid - ty * 28;          // 0..27
    const int y0 = ty * 2;
    const int x0 = tx * 2;

    // ---- prologue: fill buffer 0 with tile t0 (direct, stalls once) ----
    {
        const int plane = t0 >> 1;
        const int h0 = (t0 & 1) * HR;
        const float* __restrict__ xp = x + (size_t)plane * (H_ * W_);
        if (tid < K_ * 8) {
            int j = tid & 7;
            float2 v2 = make_float2(0.0f, 0.0f);
            if (j < K_) {
                float wv = w[(plane % C_) * (K_ * K_) + (tid >> 3) * K_ + j];
                float f2 = mant_map(wv);
                v2 = make_float2(wv, __fdividef(wv, f2));
            }
            sw[0][tid] = v2;
        }
#pragma unroll
        for (int kk = 0; kk < 6; ++kk) {
            int idx = tid + kk * NTHR;
            if (idx < CELLS) {
                int r = idx >> 6, q = idx & 63;
                int iy = h0 + r - PAD_, ix = q - PAD_;
                float v = 0.0f;
                if ((unsigned)iy < H_ && (unsigned)ix < W_) v = xp[iy * W_ + ix];
                float f1 = mant_map(v);
                float u  = __fdividef(v, f1);
                sm[0][idx] = make_float2(u, v - u);
            }
        }
    }
    __syncthreads();

    // ---- persistent tile loop ----
    for (int k = t0; k < t1; ++k) {
        const int buf = (k - t0) & 1;
        const int plane = k >> 1;
        const int h0 = (k & 1) * HR;
        const bool more = (k + 1 < t1);

        // stage A: issue next tile's global loads (6 independent LDGs)
        float v[6];
        int nplane = 0;
        if (more) {
            const int nt = k + 1;
            nplane = nt >> 1;
            const int nh0 = (nt & 1) * HR;
            const float* __restrict__ xp = x + (size_t)nplane * (H_ * W_);
#pragma unroll
            for (int kk = 0; kk < 6; ++kk) {
                int idx = tid + kk * NTHR;
                float vv = 0.0f;
                if (idx < CELLS) {
                    int r = idx >> 6, q = idx & 63;
                    int iy = nh0 + r - PAD_, ix = q - PAD_;
                    if ((unsigned)iy < H_ && (unsigned)ix < W_)
                        vv = __ldg(xp + iy * W_ + ix);
                }
                v[kk] = vv;
            }
        }

        // stage B: compute current tile from sm[buf]
        {
            const ulonglong2* __restrict__ swq = (const ulonglong2*)sw[buf];
            const float2* __restrict__ smb = sm[buf];
            unsigned long long acc00 = 0ull, acc01 = 0ull,
                               acc10 = 0ull, acc11 = 0ull;
#pragma unroll
            for (int t = 0; t < 8; ++t) {
                const unsigned long long* pr =
                    (const unsigned long long*)&smb[((y0 + t) << 6) + x0];
                unsigned long long p[8];
                ((ulonglong2*)p)[0] = ((const ulonglong2*)pr)[0];
                ((ulonglong2*)p)[1] = ((const ulonglong2*)pr)[1];
                ((ulonglong2*)p)[2] = ((const ulonglong2*)pr)[2];
                ((ulonglong2*)p)[3] = ((const ulonglong2*)pr)[3];

                // oy = 0 uses kernel row i = t (valid t<=6)
                if (t <= 6) {
#pragma unroll
                    for (int jj = 0; jj < 4; ++jj) {       // j = 2jj, 2jj+1
                        ulonglong2 wp = swq[(t << 2) + jj]; // LDS.128 broadcast
                        const int j0 = 2 * jj;
                        acc00 = fma2(p[j0],     wp.x, acc00);
                        acc01 = fma2(p[j0 + 1], wp.x, acc01);
                        if (j0 + 1 < K_) {
                            acc00 = fma2(p[j0 + 1], wp.y, acc00);
                            acc01 = fma2(p[j0 + 2], wp.y, acc01);
                        }
                    }
                }
                // oy = 1 uses kernel row i = t-1 (valid t>=1)
                if (t >= 1) {
#pragma unroll
                    for (int jj = 0; jj < 4; ++jj) {
                        ulonglong2 wp = swq[((t - 1) << 2) + jj];
                        const int j0 = 2 * jj;
                        acc10 = fma2(p[j0],     wp.x, acc10);
                        acc11 = fma2(p[j0 + 1], wp.x, acc11);
                        if (j0 + 1 < K_) {
                            acc10 = fma2(p[j0 + 1], wp.y, acc10);
                            acc11 = fma2(p[j0 + 2], wp.y, acc11);
                        }
                    }
                }
            }
            float* op = out + (size_t)plane * (H_ * W_) + (h0 + y0) * W_ + x0;
            *(float2*)(op)      = make_float2(pairsum(acc00), pairsum(acc01));
            *(float2*)(op + W_) = make_float2(pairsum(acc10), pairsum(acc11));
        }

        // stage C: mantissa-split staged regs into sm[buf^1], next weights
        if (more) {
            if (tid < K_ * 8) {
                int j = tid & 7;
                float2 v2 = make_float2(0.0f, 0.0f);
                if (j < K_) {
                    float wv = w[(nplane % C_) * (K_ * K_) + (tid >> 3) * K_ + j];
                    float f2 = mant_map(wv);
                    v2 = make_float2(wv, __fdividef(wv, f2));
                }
                sw[buf ^ 1][tid] = v2;
            }
#pragma unroll
            for (int kk = 0; kk < 6; ++kk) {
                int idx = tid + kk * NTHR;
                if (idx < CELLS) {
                    float f1 = mant_map(v[kk]);
                    float u  = __fdividef(v[kk], f1);
                    sm[buf ^ 1][idx] = make_float2(u, v[kk] - u);
                }
            }
        }
        __syncthreads();
    }
}

extern "C" void kernel_launch(void* const* d_in, const int* in_sizes, int n_in,
                              void* d_out, int out_size) {
    const float* x  = (const float*)d_in[0];   // (4,192,56,56) f32
    const float* wt = (const float*)d_in[1];   // (192,1,7,7)  f32
    float* out = (float*)d_out;                // (4,192,56,56) f32
    (void)in_sizes; (void)n_in; (void)out_size;
    waconv_kernel<<<NBLK, NTHR>>>(x, wt, out);
}

// round 11
// speedup vs baseline: 1.0204x; 1.0204x over previous
#include <cuda_runtime.h>

// Appro_WAConv2d: depthwise 7x7 conv with mantissa-approximation factor.
//   term = x*w*(f1+f2-1)/(f1*f2) = u*w + s*(w/f2),  u = x/f1, s = x - u
// Packed f32x2: smem {u,s} float2, weights {w, w/f2}; one fma.rn.f32x2/tap.
// Round-11:
//  (a) 4-row x 2-float thread tile on FULL-plane persistent tiles: each
//      loaded input row feeds 4 output rows -> input LDS wavefronts per
//      output float 1.0 -> 0.625 (input loads were 60%+ of L1 traffic).
//      Dynamic smem (2 x 31.75KB buffers), 2 blocks/SM, grid 304.
//  (b) division-free mantissa split: u = x/f1 is a signed power of two up
//      to O(1e-7) (f1 shares x's mantissa) -> 4 integer ops, no MUFU.RCP.
//      Same trick for w/f2. Error ~1e-6 rel, threshold 1e-3.

#define B_   4
#define C_   192
#define H_   56
#define W_   56
#define K_   7
#define PAD_ 3
#define SMROWS 62           // 56 + 2*3 halo rows (full plane)
#define SR    64            // smem row stride in float2 (pow2 indexing)
#define NTHR  392
#define CELLS (SMROWS * SR) // 3968
#define NTILES (B_ * C_)    // 768 full-plane tiles
#define NBLK  304           // 152 SMs * 2 resident blocks
#define LITER 11            // ceil(CELLS / NTHR)
#define SWPAD (K_ * 8)      // 56 weight pairs (7 rows padded to 8)

// division-free split: u ~= v/f1 (signed power of 2), s = v - u.
// f1 = mantissa-map(|v|+eps) shares the mantissa of a=|v|+eps, so a/f1 is
// exactly 2^(ea + topbit); dropped eps/f1 term is O(1e-7).
__device__ __forceinline__ float2 usplit(float v) {
    float a = fabsf(v) + 1e-7f;
    unsigned ab = __float_as_uint(a);
    unsigned ub = (__float_as_uint(v) & 0x80000000u)
                | ((ab & 0x7F800000u) + ((ab & 0x00400000u) << 1));
    float u = __uint_as_float(ub);
    return make_float2(u, v - u);
}

__device__ __forceinline__ unsigned long long fma2(unsigned long long a,
                                                   unsigned long long b,
                                                   unsigned long long c) {
    unsigned long long d;
    asm("fma.rn.f32x2 %0, %1, %2, %3;" : "=l"(d) : "l"(a), "l"(b), "l"(c));
    return d;
}

__device__ __forceinline__ float pairsum(unsigned long long v) {
    return __uint_as_float((unsigned)v) + __uint_as_float((unsigned)(v >> 32));
}

// dynamic smem layout: sm[2][CELLS] float2, then sw[2][SWPAD] float2
extern __shared__ __align__(16) float2 dynsm[];

__global__ __launch_bounds__(NTHR, 2)
void waconv_kernel(const float* __restrict__ x,
                   const float* __restrict__ w,
                   float* __restrict__ out) {
    float2* const sm0 = dynsm;
    float2* const sm1 = dynsm + CELLS;
    float2* const sw0 = dynsm + 2 * CELLS;
    float2* const sw1 = sw0 + SWPAD;

    const int tid = threadIdx.x;
    const int t0 = (int)(((long long)blockIdx.x       * NTILES) / NBLK);
    const int t1 = (int)(((long long)(blockIdx.x + 1) * NTILES) / NBLK);

    const int ty = tid / 28;               // 0..13
    const int tx = tid - ty * 28;          // 0..27
    const int y0 = ty * 4;                 // output rows y0..y0+3
    const int x0 = tx * 2;                 // output floats x0, x0+1

    // ---- prologue: fill buffer 0 with plane t0 ----
    {
        const float* __restrict__ xp = x + (size_t)t0 * (H_ * W_);
        if (tid < SWPAD) {
            int j = tid & 7;
            float2 v2 = make_float2(0.0f, 0.0f);
            if (j < K_) {
                float wv = w[(t0 % C_) * (K_ * K_) + (tid >> 3) * K_ + j];
                v2 = make_float2(wv, usplit(wv).x);   // {w, ~w/f2}
            }
            sw0[tid] = v2;
        }
#pragma unroll
        for (int kk = 0; kk < LITER; ++kk) {
            int idx = tid + kk * NTHR;
            if (idx < CELLS) {
                int r = idx >> 6, q = idx & 63;
                int iy = r - PAD_, ix = q - PAD_;
                float v = 0.0f;
                if ((unsigned)iy < H_ && (unsigned)ix < W_) v = xp[iy * W_ + ix];
                sm0[idx] = usplit(v);
            }
        }
    }
    __syncthreads();

    // ---- persistent tile loop ----
    for (int k = t0; k < t1; ++k) {
        const int buf = (k - t0) & 1;
        const float2* __restrict__ smb = buf ? sm1 : sm0;
        const ulonglong2* __restrict__ swq =
            (const ulonglong2*)(buf ? sw1 : sw0);
        float2* const smn = buf ? sm0 : sm1;
        float2* const swn = buf ? sw0 : sw1;
        const bool more = (k + 1 < t1);

        // stage A: issue next plane's global loads (LITER independent LDGs)
        float v[LITER];
        if (more) {
            const float* __restrict__ xp = x + (size_t)(k + 1) * (H_ * W_);
#pragma unroll
            for (int kk = 0; kk < LITER; ++kk) {
                int idx = tid + kk * NTHR;
                float vv = 0.0f;
                if (idx < CELLS) {
                    int r = idx >> 6, q = idx & 63;
                    int iy = r - PAD_, ix = q - PAD_;
                    if ((unsigned)iy < H_ && (unsigned)ix < W_)
                        vv = __ldg(xp + iy * W_ + ix);
                }
                v[kk] = vv;
            }
        }

        // stage B: compute 4x2 tile from smb
        {
            unsigned long long acc[4][2];
#pragma unroll
            for (int a = 0; a < 4; ++a) { acc[a][0] = 0ull; acc[a][1] = 0ull; }

#pragma unroll
            for (int t = 0; t < 10; ++t) {       // input row = y0 + t
                const unsigned long long* pr =
                    (const unsigned long long*)&smb[((y0 + t) << 6) + x0];
                unsigned long long p[8];
                ((ulonglong2*)p)[0] = ((const ulonglong2*)pr)[0];
                ((ulonglong2*)p)[1] = ((const ulonglong2*)pr)[1];
                ((ulonglong2*)p)[2] = ((const ulonglong2*)pr)[2];
                ((ulonglong2*)p)[3] = ((const ulonglong2*)pr)[3];
#pragma unroll
                for (int oy = 0; oy < 4; ++oy) {
                    const int i = t - oy;        // kernel row, compile-time
                    if (i < 0 || i > 6) continue;
#pragma unroll
                    for (int jj = 0; jj < 4; ++jj) {
                        ulonglong2 wp = swq[(i << 2) + jj];  // broadcast
                        const int j0 = 2 * jj;
                        acc[oy][0] = fma2(p[j0],     wp.x, acc[oy][0]);
                        acc[oy][1] = fma2(p[j0 + 1], wp.x, acc[oy][1]);
                        if (j0 + 1 < K_) {
                            acc[oy][0] = fma2(p[j0 + 1], wp.y, acc[oy][0]);
                            acc[oy][1] = fma2(p[j0 + 2], wp.y, acc[oy][1]);
                        }
                    }
                }
            }
            float* op = out + (size_t)k * (H_ * W_) + y0 * W_ + x0;
#pragma unroll
            for (int oy = 0; oy < 4; ++oy)
                *(float2*)(op + oy * W_) =
                    make_float2(pairsum(acc[oy][0]), pairsum(acc[oy][1]));
        }

        // stage C: split staged regs into the other buffer + next weights
        if (more) {
            if (tid < SWPAD) {
                int j = tid & 7;
                float2 v2 = make_float2(0.0f, 0.0f);
                if (j < K_) {
                    float wv = w[((k + 1) % C_) * (K_ * K_) + (tid >> 3) * K_ + j];
                    v2 = make_float2(wv, usplit(wv).x);
                }
                swn[tid] = v2;
            }
#pragma unroll
            for (int kk = 0; kk < LITER; ++kk) {
                int idx = tid + kk * NTHR;
                if (idx < CELLS) smn[idx] = usplit(v[kk]);
            }
        }
        __syncthreads();
    }
}

#define SMEM_BYTES ((2 * CELLS + 2 * SWPAD) * (int)sizeof(float2))

extern "C" void kernel_launch(void* const* d_in, const int* in_sizes, int n_in,
                              void* d_out, int out_size) {
    const float* x  = (const float*)d_in[0];   // (4,192,56,56) f32
    const float* wt = (const float*)d_in[1];   // (192,1,7,7)  f32
    float* out = (float*)d_out;                // (4,192,56,56) f32
    (void)in_sizes; (void)n_in; (void)out_size;
    static int configured = 0;
    if (!configured) {
        cudaFuncSetAttribute(waconv_kernel,
                             cudaFuncAttributeMaxDynamicSharedMemorySize,
                             SMEM_BYTES);
        configured = 1;
    }
    waconv_kernel<<<NBLK, NTHR, SMEM_BYTES>>>(x, wt, out);
}